// round 1
// baseline (speedup 1.0000x reference)
#include <cuda_runtime.h>
#include <math.h>

#define BG     64
#define NG     1000
#define NTOT   64000
#define KNN    10
#define NLAYER 4
#define EMB    128
#define EALL   (NTOT*KNN)   /* 640000 */

// ----------------------------- scratch (device globals) -----------------------------
__device__ float g_h   [NTOT*EMB];          // current node embeddings (normalized)
__device__ float g_h2  [NTOT*EMB];          // pre-norm update output
__device__ float g_magg[NTOT*EMB];          // aggregated messages
__device__ float g_pos [NTOT*2];            // current positions
__device__ float g_msg [(size_t)EALL*EMB];  // per-edge messages (327.7 MB)
__device__ float g_pd  [EALL*2];            // gated pos diffs
__device__ int   g_src [EALL];              // knn source list
__device__ int   g_rowptr[NTOT+1];
__device__ int   g_cnt [NTOT];
__device__ int   g_fill[NTOT];
__device__ int   g_perm[EALL];
__device__ float g_colsum[EMB];
__device__ float g_sumsq;
__device__ float g_mu[EMB];
__device__ float g_inv;

// ----------------------------- embed: h = relu(h_feat @ W_emb + b_emb) --------------
__global__ void k_embed(const float* __restrict__ hf, const float* __restrict__ We,
                        const float* __restrict__ be)
{
    int idx = blockIdx.x*blockDim.x + threadIdx.x;
    if (idx >= NTOT*EMB) return;
    int n = idx >> 7, c = idx & 127;
    float s = be[c];
    #pragma unroll
    for (int k = 0; k < 5; k++) s += hf[n*5+k] * We[k*EMB+c];
    g_h[idx] = fmaxf(s, 0.f);
}

__global__ void k_copy_pos(const float* __restrict__ pos)
{
    int idx = blockIdx.x*blockDim.x + threadIdx.x;
    if (idx < NTOT*2) g_pos[idx] = pos[idx];
}

// ----------------------------- layer-0 CSR build -----------------------------------
__global__ void k_zero_csr()
{
    int idx = blockIdx.x*blockDim.x + threadIdx.x;
    if (idx < NTOT) { g_cnt[idx] = 0; g_fill[idx] = 0; }
}

__global__ void k_count(const int* __restrict__ dst)
{
    int e = blockIdx.x*blockDim.x + threadIdx.x;
    if (e < EALL) atomicAdd(&g_cnt[dst[e]], 1);
}

__global__ void k_scan()   // 1 block, 1024 threads
{
    __shared__ int part[1024];
    const int CH = 63;
    int t = threadIdx.x;
    int beg = t*CH, end = min(beg + CH, NTOT);
    int s = 0;
    for (int i = beg; i < end; i++) s += g_cnt[i];
    part[t] = s;
    __syncthreads();
    if (t == 0) {
        int run = 0;
        for (int i = 0; i < 1024; i++) { int v = part[i]; part[i] = run; run += v; }
    }
    __syncthreads();
    int run = part[t];
    for (int i = beg; i < end; i++) { g_rowptr[i] = run; run += g_cnt[i]; }
    if (t == 0) g_rowptr[NTOT] = EALL;
}

__global__ void k_fill(const int* __restrict__ dst)
{
    int e = blockIdx.x*blockDim.x + threadIdx.x;
    if (e >= EALL) return;
    int d = dst[e];
    int o = atomicAdd(&g_fill[d], 1);
    g_perm[g_rowptr[d] + o] = e;
}

// ----------------------------- kNN (warp per center node) --------------------------
__global__ void k_knn()
{
    __shared__ float2 sp[NG];
    int g  = blockIdx.x / (NG/4);
    int nb = blockIdx.x % (NG/4);
    for (int i = threadIdx.x; i < NG; i += 128)
        sp[i] = ((const float2*)g_pos)[g*NG + i];
    __syncthreads();
    int w = threadIdx.x >> 5, lane = threadIdx.x & 31;
    int i = nb*4 + w;
    float2 pi = sp[i];
    float bd[KNN]; int bj[KNN];
    #pragma unroll
    for (int r = 0; r < KNN; r++) { bd[r] = 3.4e38f; bj[r] = 0x7fffffff; }
    for (int j = lane; j < NG; j += 32) {
        if (j == i) continue;
        float dx = pi.x - sp[j].x, dy = pi.y - sp[j].y;
        float d2 = dx*dx + dy*dy;
        if (d2 < bd[KNN-1] || (d2 == bd[KNN-1] && j < bj[KNN-1])) {
            int r = KNN-1;
            while (r > 0 && (d2 < bd[r-1] || (d2 == bd[r-1] && j < bj[r-1]))) {
                bd[r] = bd[r-1]; bj[r] = bj[r-1]; r--;
            }
            bd[r] = d2; bj[r] = j;
        }
    }
    int head = 0;
    int base = (g*NG + i)*KNN;
    for (int r = 0; r < KNN; r++) {
        float d = (head < KNN) ? bd[head] : 3.4e38f;
        int   j = (head < KNN) ? bj[head] : 0x7fffffff;
        float dm = d; int jm = j;
        #pragma unroll
        for (int off = 16; off >= 1; off >>= 1) {
            float od = __shfl_xor_sync(0xffffffffu, dm, off);
            int   oj = __shfl_xor_sync(0xffffffffu, jm, off);
            if (od < dm || (od == dm && oj < jm)) { dm = od; jm = oj; }
        }
        if (jm == j && dm == d && head < KNN) head++;
        if (lane == 0) g_src[base + r] = g*NG + jm;
    }
}

// ----------------------------- fused message GEMM ----------------------------------
// msg = relu([h_dst | h_src | dist] @ Wm + bm); gate = relu(msg @ Wp + bp);
// writes msg buffer + gated pos_diff buffer. 64 edges x 128 cols per block.
__global__ __launch_bounds__(256) void k_message(
    const int* __restrict__ srcA, const int* __restrict__ dstA,
    const float* __restrict__ Wm, const float* __restrict__ bm,
    const float* __restrict__ Wp, const float* __restrict__ bp)
{
    __shared__ __align__(16) float Xs[16][68];
    __shared__ __align__(16) float Ws[16*EMB];
    __shared__ int   sSrc[64], sDst[64];
    __shared__ float sDist[64], sPdx[64], sPdy[64];
    __shared__ float sBm[128], sWlast[128], sWp[256], sBp[2];

    int t  = threadIdx.x;
    int e0 = blockIdx.x * 64;
    const int* srcP = srcA ? srcA : g_src;

    if (t < 64) {
        int e = e0 + t;
        int s = srcP[e];
        int d = dstA ? dstA[e] : e / KNN;
        sSrc[t] = s; sDst[t] = d;
        float px = g_pos[2*d]   - g_pos[2*s];
        float py = g_pos[2*d+1] - g_pos[2*s+1];
        sPdx[t] = px; sPdy[t] = py;
        sDist[t] = sqrtf(px*px + py*py);
    }
    if (t < 128) { sBm[t] = bm[t]; sWlast[t] = Wm[256*EMB + t]; }
    sWp[t] = Wp[t];                 // blockDim == 256 == EMB*2
    if (t < 2) sBp[t] = bp[t];

    float acc[4][8];
    #pragma unroll
    for (int j = 0; j < 4; j++)
        #pragma unroll
        for (int i = 0; i < 8; i++) acc[j][i] = 0.f;

    int ty = t >> 4, tx = t & 15;
    __syncthreads();

    #pragma unroll 1
    for (int kc = 0; kc < 16; kc++) {
        const float4* w4 = (const float4*)(Wm + kc*16*EMB);
        ((float4*)Ws)[t]       = w4[t];
        ((float4*)Ws)[t + 256] = w4[t + 256];
        {
            int e = t >> 2, q = t & 3;
            int k = kc*16 + q*4;
            int node = (k < 128) ? sDst[e] : sSrc[e];
            float4 v = *(const float4*)(g_h + node*EMB + (k & 127));
            Xs[q*4+0][e] = v.x; Xs[q*4+1][e] = v.y;
            Xs[q*4+2][e] = v.z; Xs[q*4+3][e] = v.w;
        }
        __syncthreads();
        #pragma unroll
        for (int kk = 0; kk < 16; kk++) {
            float4 xv = *(const float4*)(&Xs[kk][ty*4]);
            float4 wa = *(const float4*)(&Ws[kk*EMB + tx*4]);
            float4 wb = *(const float4*)(&Ws[kk*EMB + 64 + tx*4]);
            float xs[4] = {xv.x, xv.y, xv.z, xv.w};
            float ws[8] = {wa.x, wa.y, wa.z, wa.w, wb.x, wb.y, wb.z, wb.w};
            #pragma unroll
            for (int j = 0; j < 4; j++)
                #pragma unroll
                for (int i = 0; i < 8; i++)
                    acc[j][i] = fmaf(xs[j], ws[i], acc[j][i]);
        }
        __syncthreads();
    }

    // epilogue: dist term + bias + relu + gate partials
    float gp[4][2];
    #pragma unroll
    for (int j = 0; j < 4; j++) {
        int e = ty*4 + j;
        float de = sDist[e];
        gp[j][0] = 0.f; gp[j][1] = 0.f;
        #pragma unroll
        for (int i = 0; i < 8; i++) {
            int c = (i < 4) ? tx*4 + i : 64 + tx*4 + (i - 4);
            float v = acc[j][i] + de*sWlast[c] + sBm[c];
            v = fmaxf(v, 0.f);
            acc[j][i] = v;
            gp[j][0] += v * sWp[2*c];
            gp[j][1] += v * sWp[2*c+1];
        }
    }
    #pragma unroll
    for (int off = 8; off >= 1; off >>= 1) {
        #pragma unroll
        for (int j = 0; j < 4; j++) {
            gp[j][0] += __shfl_xor_sync(0xffffffffu, gp[j][0], off);
            gp[j][1] += __shfl_xor_sync(0xffffffffu, gp[j][1], off);
        }
    }
    #pragma unroll
    for (int j = 0; j < 4; j++) {
        int e  = ty*4 + j;
        int eg = e0 + e;
        if (tx == 0) {
            float g0 = fmaxf(gp[j][0] + sBp[0], 0.f);
            float g1 = fmaxf(gp[j][1] + sBp[1], 0.f);
            g_pd[2*eg]   = sPdx[e] * g0;
            g_pd[2*eg+1] = sPdy[e] * g1;
        }
        float* mb = g_msg + (size_t)eg*EMB;
        *(float4*)(mb + tx*4)      = make_float4(acc[j][0], acc[j][1], acc[j][2], acc[j][3]);
        *(float4*)(mb + 64 + tx*4) = make_float4(acc[j][4], acc[j][5], acc[j][6], acc[j][7]);
    }
}

// ----------------------------- aggregation (no atomics) ----------------------------
__global__ void k_aggregate(int use_csr)
{
    int n = blockIdx.x*4 + (threadIdx.x >> 7);
    int c = threadIdx.x & 127;
    int beg, deg;
    if (use_csr) { beg = g_rowptr[n]; deg = g_rowptr[n+1] - beg; }
    else         { beg = n*KNN;       deg = KNN; }
    float s = 0.f;
    for (int k = 0; k < deg; k++) {
        int e = use_csr ? g_perm[beg + k] : beg + k;
        s += g_msg[(size_t)e*EMB + c];
    }
    g_magg[n*EMB + c] = s;
    if (c < 2) {
        float p = 0.f;
        for (int k = 0; k < deg; k++) {
            int e = use_csr ? g_perm[beg + k] : beg + k;
            p += g_pd[2*e + c];
        }
        g_pos[2*n + c] += p / fmaxf((float)deg, 1.f);
    }
}

// ----------------------------- update GEMM + pairnorm stats ------------------------
__global__ __launch_bounds__(256) void k_update(
    const float* __restrict__ Wu, const float* __restrict__ bu)
{
    __shared__ __align__(16) float Xs[16][68];
    __shared__ __align__(16) float Ws[16*EMB];
    __shared__ float sBu[128];
    __shared__ float sCol[128];
    __shared__ float sSq;

    int t  = threadIdx.x;
    int n0 = blockIdx.x * 64;
    if (t < 128) { sBu[t] = bu[t]; sCol[t] = 0.f; }
    if (t == 0) sSq = 0.f;

    float acc[4][8];
    #pragma unroll
    for (int j = 0; j < 4; j++)
        #pragma unroll
        for (int i = 0; i < 8; i++) acc[j][i] = 0.f;

    int ty = t >> 4, tx = t & 15;
    __syncthreads();

    #pragma unroll 1
    for (int kc = 0; kc < 16; kc++) {
        const float4* w4 = (const float4*)(Wu + kc*16*EMB);
        ((float4*)Ws)[t]       = w4[t];
        ((float4*)Ws)[t + 256] = w4[t + 256];
        {
            int r = t >> 2, q = t & 3;
            int k = kc*16 + q*4;
            int node = n0 + r;
            const float* base = (k < 128) ? (g_h + node*EMB + k)
                                          : (g_magg + node*EMB + (k - 128));
            float4 v = *(const float4*)base;
            Xs[q*4+0][r] = v.x; Xs[q*4+1][r] = v.y;
            Xs[q*4+2][r] = v.z; Xs[q*4+3][r] = v.w;
        }
        __syncthreads();
        #pragma unroll
        for (int kk = 0; kk < 16; kk++) {
            float4 xv = *(const float4*)(&Xs[kk][ty*4]);
            float4 wa = *(const float4*)(&Ws[kk*EMB + tx*4]);
            float4 wb = *(const float4*)(&Ws[kk*EMB + 64 + tx*4]);
            float xs[4] = {xv.x, xv.y, xv.z, xv.w};
            float ws[8] = {wa.x, wa.y, wa.z, wa.w, wb.x, wb.y, wb.z, wb.w};
            #pragma unroll
            for (int j = 0; j < 4; j++)
                #pragma unroll
                for (int i = 0; i < 8; i++)
                    acc[j][i] = fmaf(xs[j], ws[i], acc[j][i]);
        }
        __syncthreads();
    }

    float sq = 0.f;
    #pragma unroll
    for (int j = 0; j < 4; j++) {
        int n = n0 + ty*4 + j;
        #pragma unroll
        for (int i = 0; i < 8; i++) {
            int c = (i < 4) ? tx*4 + i : 64 + tx*4 + (i - 4);
            float v = fmaxf(acc[j][i] + sBu[c], 0.f);
            acc[j][i] = v;
            sq += v*v;
        }
        float* o = g_h2 + (size_t)n*EMB;
        *(float4*)(o + tx*4)      = make_float4(acc[j][0], acc[j][1], acc[j][2], acc[j][3]);
        *(float4*)(o + 64 + tx*4) = make_float4(acc[j][4], acc[j][5], acc[j][6], acc[j][7]);
    }
    #pragma unroll
    for (int i = 0; i < 8; i++) {
        int c = (i < 4) ? tx*4 + i : 64 + tx*4 + (i - 4);
        atomicAdd(&sCol[c], acc[0][i] + acc[1][i] + acc[2][i] + acc[3][i]);
    }
    #pragma unroll
    for (int off = 16; off >= 1; off >>= 1)
        sq += __shfl_xor_sync(0xffffffffu, sq, off);
    if ((t & 31) == 0) atomicAdd(&sSq, sq);
    __syncthreads();
    if (t < 128) atomicAdd(&g_colsum[t], sCol[t]);
    if (t == 0)  atomicAdd(&g_sumsq, sSq);
}

__global__ void k_stats_zero()
{
    int t = threadIdx.x;
    if (t < 128) g_colsum[t] = 0.f;
    if (t == 0)  g_sumsq = 0.f;
}

__global__ void k_stats_final()   // 1 block, 128 threads
{
    __shared__ float red[4];
    int t = threadIdx.x;
    float mu = g_colsum[t] * (1.0f/(float)NTOT);
    g_mu[t] = mu;
    float m2 = mu*mu;
    #pragma unroll
    for (int off = 16; off >= 1; off >>= 1)
        m2 += __shfl_xor_sync(0xffffffffu, m2, off);
    if ((t & 31) == 0) red[t >> 5] = m2;
    __syncthreads();
    if (t == 0) {
        float tot = red[0] + red[1] + red[2] + red[3];
        float var = (g_sumsq - (float)NTOT * tot) * (1.0f/(float)NTOT) + 1e-5f;
        g_inv = 1.0f / sqrtf(var);
    }
}

__global__ void k_normalize()
{
    int idx = blockIdx.x*blockDim.x + threadIdx.x;
    if (idx >= NTOT*EMB) return;
    g_h[idx] = (g_h2[idx] - g_mu[idx & 127]) * g_inv;
}

// ----------------------------- readout: maxpool + MLP ------------------------------
__global__ void k_final(const float* __restrict__ W1, const float* __restrict__ b1,
                        const float* __restrict__ W2, const float* __restrict__ b2,
                        float* __restrict__ out)
{
    int g = blockIdx.x, c = threadIdx.x;
    const float* hb = g_h + (size_t)g*NG*EMB;
    float m0 = -3.4e38f, m1 = -3.4e38f, m2 = -3.4e38f, m3 = -3.4e38f;
    for (int n = 0; n < NG; n += 4) {
        m0 = fmaxf(m0, hb[(n+0)*EMB + c]);
        m1 = fmaxf(m1, hb[(n+1)*EMB + c]);
        m2 = fmaxf(m2, hb[(n+2)*EMB + c]);
        m3 = fmaxf(m3, hb[(n+3)*EMB + c]);
    }
    __shared__ float shg[128], shid[128];
    shg[c] = fmaxf(fmaxf(m0, m1), fmaxf(m2, m3));
    __syncthreads();
    float s = b1[c];
    #pragma unroll 4
    for (int k = 0; k < 128; k++) s += shg[k] * W1[k*EMB + c];
    shid[c] = fmaxf(s, 0.f);
    __syncthreads();
    if (c < 2) {
        float o = b2[c];
        for (int k = 0; k < 128; k++) o += shid[k] * W2[2*k + c];
        out[2*g + c] = o;
    }
}

// ----------------------------- launch sequence -------------------------------------
extern "C" void kernel_launch(void* const* d_in, const int* in_sizes, int n_in,
                              void* d_out, int out_size)
{
    const float* h_feat = (const float*)d_in[0];
    const float* pos    = (const float*)d_in[1];
    const int*   edge   = (const int*)  d_in[2];
    const float* W_emb  = (const float*)d_in[3];
    const float* b_emb  = (const float*)d_in[4];
    const float* W_msg  = (const float*)d_in[5];
    const float* b_msg  = (const float*)d_in[6];
    const float* W_pos  = (const float*)d_in[7];
    const float* b_pos  = (const float*)d_in[8];
    const float* W_upd  = (const float*)d_in[9];
    const float* b_upd  = (const float*)d_in[10];
    const float* W1     = (const float*)d_in[11];
    const float* b1     = (const float*)d_in[12];
    const float* W2     = (const float*)d_in[13];
    const float* b2     = (const float*)d_in[14];
    float* out = (float*)d_out;

    k_embed<<<(NTOT*EMB + 255)/256, 256>>>(h_feat, W_emb, b_emb);
    k_copy_pos<<<(NTOT*2 + 255)/256, 256>>>(pos);

    for (int l = 0; l < NLAYER; l++) {
        const int* srcA = nullptr;
        const int* dstA = nullptr;
        if (l == 0) {
            k_zero_csr<<<(NTOT + 255)/256, 256>>>();
            k_count<<<(EALL + 255)/256, 256>>>(edge + EALL);
            k_scan<<<1, 1024>>>();
            k_fill<<<(EALL + 255)/256, 256>>>(edge + EALL);
            srcA = edge;            // edge_index[0]
            dstA = edge + EALL;     // edge_index[1]
        } else {
            k_knn<<<BG*(NG/4), 128>>>();
        }
        k_message<<<EALL/64, 256>>>(srcA, dstA,
                                    W_msg + (size_t)l*257*EMB, b_msg + l*EMB,
                                    W_pos + l*EMB*2,          b_pos + l*2);
        k_aggregate<<<NTOT/4, 512>>>(l == 0 ? 1 : 0);
        k_stats_zero<<<1, 128>>>();
        k_update<<<NTOT/64, 256>>>(W_upd + (size_t)l*256*EMB, b_upd + l*EMB);
        k_stats_final<<<1, 128>>>();
        k_normalize<<<(NTOT*EMB + 255)/256, 256>>>();
    }
    k_final<<<BG, 128>>>(W1, b1, W2, b2, out);
}

// round 3
// speedup vs baseline: 1.8186x; 1.8186x over previous
#include <cuda_runtime.h>
#include <math.h>

#define BG     64
#define NG     1000
#define NTOT   64000
#define KNN    10
#define NLAYER 4
#define EMB    128
#define EALL   (NTOT*KNN)   /* 640000 */

// ----------------------------- scratch (device globals) -----------------------------
__device__ float g_h   [NTOT*EMB];          // current node embeddings (normalized)
__device__ float g_h2  [NTOT*EMB];          // pre-norm update output
__device__ float g_magg[NTOT*EMB];          // aggregated messages
__device__ float g_p1  [NTOT*EMB];          // h @ Wm1 + bm   (dst contribution)
__device__ float g_p2  [NTOT*EMB];          // h @ Wm2        (src contribution)
__device__ float g_posA[NTOT*2];
__device__ float g_posB[NTOT*2];
__device__ int   g_src [EALL];              // knn source list
__device__ int   g_rowptr[NTOT+1];
__device__ int   g_cnt [NTOT];
__device__ int   g_fill[NTOT];
__device__ int   g_perm[EALL];
__device__ float g_colsum[EMB];
__device__ float g_sumsq;
__device__ float g_mu[EMB];
__device__ float g_inv;

// ----------------------------- embed -----------------------------------------------
__global__ void k_embed(const float* __restrict__ hf, const float* __restrict__ We,
                        const float* __restrict__ be)
{
    int idx = blockIdx.x*blockDim.x + threadIdx.x;
    if (idx >= NTOT*EMB) return;
    int n = idx >> 7, c = idx & 127;
    float s = be[c];
    #pragma unroll
    for (int k = 0; k < 5; k++) s += hf[n*5+k] * We[k*EMB+c];
    g_h[idx] = fmaxf(s, 0.f);
}

__global__ void k_copy_pos(const float* __restrict__ pos)
{
    int idx = blockIdx.x*blockDim.x + threadIdx.x;
    if (idx < NTOT*2) g_posA[idx] = pos[idx];
}

// ----------------------------- layer-0 CSR build -----------------------------------
__global__ void k_zero_csr()
{
    int idx = blockIdx.x*blockDim.x + threadIdx.x;
    if (idx < NTOT) { g_cnt[idx] = 0; g_fill[idx] = 0; }
}
__global__ void k_count(const int* __restrict__ dst)
{
    int e = blockIdx.x*blockDim.x + threadIdx.x;
    if (e < EALL) atomicAdd(&g_cnt[dst[e]], 1);
}
__global__ void k_scan()   // 1 block, 1024 threads
{
    __shared__ int part[1024];
    const int CH = 63;
    int t = threadIdx.x;
    int beg = t*CH, end = min(beg + CH, NTOT);
    int s = 0;
    for (int i = beg; i < end; i++) s += g_cnt[i];
    part[t] = s;
    __syncthreads();
    if (t == 0) {
        int run = 0;
        for (int i = 0; i < 1024; i++) { int v = part[i]; part[i] = run; run += v; }
    }
    __syncthreads();
    int run = part[t];
    for (int i = beg; i < end; i++) { g_rowptr[i] = run; run += g_cnt[i]; }
    if (t == 0) g_rowptr[NTOT] = EALL;
}
__global__ void k_fill(const int* __restrict__ dst)
{
    int e = blockIdx.x*blockDim.x + threadIdx.x;
    if (e >= EALL) return;
    int d = dst[e];
    int o = atomicAdd(&g_fill[d], 1);
    g_perm[g_rowptr[d] + o] = e;
}

// ----------------------------- kNN (warp per center node) --------------------------
__global__ void k_knn(const float* __restrict__ pos)
{
    __shared__ float2 sp[NG];
    int g  = blockIdx.x / (NG/4);
    int nb = blockIdx.x % (NG/4);
    for (int i = threadIdx.x; i < NG; i += 128)
        sp[i] = ((const float2*)pos)[g*NG + i];
    __syncthreads();
    int w = threadIdx.x >> 5, lane = threadIdx.x & 31;
    int i = nb*4 + w;
    float2 pi = sp[i];
    float bd[KNN]; int bj[KNN];
    #pragma unroll
    for (int r = 0; r < KNN; r++) { bd[r] = 3.4e38f; bj[r] = 0x7fffffff; }
    for (int j = lane; j < NG; j += 32) {
        if (j == i) continue;
        float dx = pi.x - sp[j].x, dy = pi.y - sp[j].y;
        float d2 = dx*dx + dy*dy;
        if (d2 < bd[KNN-1] || (d2 == bd[KNN-1] && j < bj[KNN-1])) {
            int r = KNN-1;
            while (r > 0 && (d2 < bd[r-1] || (d2 == bd[r-1] && j < bj[r-1]))) {
                bd[r] = bd[r-1]; bj[r] = bj[r-1]; r--;
            }
            bd[r] = d2; bj[r] = j;
        }
    }
    int head = 0;
    int base = (g*NG + i)*KNN;
    for (int r = 0; r < KNN; r++) {
        float d = (head < KNN) ? bd[head] : 3.4e38f;
        int   j = (head < KNN) ? bj[head] : 0x7fffffff;
        float dm = d; int jm = j;
        #pragma unroll
        for (int off = 16; off >= 1; off >>= 1) {
            float od = __shfl_xor_sync(0xffffffffu, dm, off);
            int   oj = __shfl_xor_sync(0xffffffffu, jm, off);
            if (od < dm || (od == dm && oj < jm)) { dm = od; jm = oj; }
        }
        if (jm == j && dm == d && head < KNN) head++;
        if (lane == 0) g_src[base + r] = g*NG + jm;
    }
}

// ----------------------------- node GEMM: P1/P2 ------------------------------------
// 2000 blocks: first 1000 -> g_p1 = h@Wm1 + bm, last 1000 -> g_p2 = h@Wm2.
__global__ __launch_bounds__(256) void k_pgemm(
    const float* __restrict__ Wm, const float* __restrict__ bm)
{
    __shared__ __align__(16) float Xs[16][68];
    __shared__ __align__(16) float Ws[16*EMB];
    __shared__ float sB[128];

    int t = threadIdx.x;
    int half = blockIdx.x >= 1000;
    int n0 = (blockIdx.x - half*1000) * 64;
    const float* W = Wm + half*EMB*EMB;     // rows 0..127 (dst) or 128..255 (src)
    float* C = half ? g_p2 : g_p1;

    if (t < 128) sB[t] = half ? 0.f : bm[t];

    float acc[4][8];
    #pragma unroll
    for (int j = 0; j < 4; j++)
        #pragma unroll
        for (int i = 0; i < 8; i++) acc[j][i] = 0.f;

    int ty = t >> 4, tx = t & 15;
    __syncthreads();

    #pragma unroll 1
    for (int kc = 0; kc < 8; kc++) {
        const float4* w4 = (const float4*)(W + kc*16*EMB);
        ((float4*)Ws)[t]       = w4[t];
        ((float4*)Ws)[t + 256] = w4[t + 256];
        {
            int r = t >> 2, q = t & 3;
            int k = kc*16 + q*4;
            float4 v = *(const float4*)(g_h + (n0 + r)*EMB + k);
            Xs[q*4+0][r] = v.x; Xs[q*4+1][r] = v.y;
            Xs[q*4+2][r] = v.z; Xs[q*4+3][r] = v.w;
        }
        __syncthreads();
        #pragma unroll
        for (int kk = 0; kk < 16; kk++) {
            float4 xv = *(const float4*)(&Xs[kk][ty*4]);
            float4 wa = *(const float4*)(&Ws[kk*EMB + tx*4]);
            float4 wb = *(const float4*)(&Ws[kk*EMB + 64 + tx*4]);
            float xs[4] = {xv.x, xv.y, xv.z, xv.w};
            float ws[8] = {wa.x, wa.y, wa.z, wa.w, wb.x, wb.y, wb.z, wb.w};
            #pragma unroll
            for (int j = 0; j < 4; j++)
                #pragma unroll
                for (int i = 0; i < 8; i++)
                    acc[j][i] = fmaf(xs[j], ws[i], acc[j][i]);
        }
        __syncthreads();
    }

    #pragma unroll
    for (int j = 0; j < 4; j++) {
        int n = n0 + ty*4 + j;
        float* o = C + (size_t)n*EMB;
        *(float4*)(o + tx*4) = make_float4(
            acc[j][0] + sB[tx*4+0], acc[j][1] + sB[tx*4+1],
            acc[j][2] + sB[tx*4+2], acc[j][3] + sB[tx*4+3]);
        *(float4*)(o + 64 + tx*4) = make_float4(
            acc[j][4] + sB[64+tx*4+0], acc[j][5] + sB[64+tx*4+1],
            acc[j][6] + sB[64+tx*4+2], acc[j][7] + sB[64+tx*4+3]);
    }
}

// ----------------------------- fused edge kernel -----------------------------------
// warp per dst node: msg_aggr[n] = sum_j relu(P1[n] + P2[j] + dist*wl + 0)
// (bm folded into P1). Gate MLP + gated mean pos update inline.
__global__ __launch_bounds__(256) void k_edge(
    int use_csr, const int* __restrict__ edge0,
    const float* __restrict__ pos_in, float* __restrict__ pos_out,
    const float* __restrict__ Wlast, const float* __restrict__ Wp,
    const float* __restrict__ bp)
{
    int warp = (blockIdx.x*blockDim.x + threadIdx.x) >> 5;
    int lane = threadIdx.x & 31;
    if (warp >= NTOT) return;
    int n = warp;

    float4 p1  = *(const float4*)(g_p1 + (size_t)n*EMB + lane*4);
    float4 wl  = *(const float4*)(Wlast + lane*4);
    float4 wpA = *(const float4*)(Wp + lane*8);       // channels 4l, 4l+1
    float4 wpB = *(const float4*)(Wp + lane*8 + 4);   // channels 4l+2, 4l+3
    float bp0 = bp[0], bp1 = bp[1];

    float px_i = pos_in[2*n], py_i = pos_in[2*n+1];

    int beg, deg;
    if (use_csr) { beg = g_rowptr[n]; deg = g_rowptr[n+1] - beg; }
    else         { beg = n*KNN;       deg = KNN; }

    float4 macc = make_float4(0.f, 0.f, 0.f, 0.f);
    float paccx = 0.f, paccy = 0.f;

    for (int k = 0; k < deg; k++) {
        int j = use_csr ? edge0[g_perm[beg + k]] : g_src[beg + k];
        float dx = px_i - pos_in[2*j];
        float dy = py_i - pos_in[2*j+1];
        float dist = sqrtf(dx*dx + dy*dy);
        float4 p2 = *(const float4*)(g_p2 + (size_t)j*EMB + lane*4);
        float v0 = fmaxf(fmaf(dist, wl.x, p1.x + p2.x), 0.f);
        float v1 = fmaxf(fmaf(dist, wl.y, p1.y + p2.y), 0.f);
        float v2 = fmaxf(fmaf(dist, wl.z, p1.z + p2.z), 0.f);
        float v3 = fmaxf(fmaf(dist, wl.w, p1.w + p2.w), 0.f);
        macc.x += v0; macc.y += v1; macc.z += v2; macc.w += v3;
        float g0 = v0*wpA.x + v1*wpA.z + v2*wpB.x + v3*wpB.z;
        float g1 = v0*wpA.y + v1*wpA.w + v2*wpB.y + v3*wpB.w;
        #pragma unroll
        for (int off = 16; off >= 1; off >>= 1) {
            g0 += __shfl_xor_sync(0xffffffffu, g0, off);
            g1 += __shfl_xor_sync(0xffffffffu, g1, off);
        }
        if (lane == 0) {
            float gate0 = fmaxf(g0 + bp0, 0.f);
            float gate1 = fmaxf(g1 + bp1, 0.f);
            paccx = fmaf(dx, gate0, paccx);
            paccy = fmaf(dy, gate1, paccy);
        }
    }
    *(float4*)(g_magg + (size_t)n*EMB + lane*4) = macc;
    if (lane == 0) {
        float inv = 1.f / fmaxf((float)deg, 1.f);
        pos_out[2*n]   = px_i + paccx*inv;
        pos_out[2*n+1] = py_i + paccy*inv;
    }
}

// ----------------------------- update GEMM + pairnorm stats ------------------------
__global__ __launch_bounds__(256) void k_update(
    const float* __restrict__ Wu, const float* __restrict__ bu)
{
    __shared__ __align__(16) float Xs[16][68];
    __shared__ __align__(16) float Ws[16*EMB];
    __shared__ float sBu[128];
    __shared__ float sCol[128];
    __shared__ float sSq;

    int t  = threadIdx.x;
    int n0 = blockIdx.x * 64;
    if (t < 128) { sBu[t] = bu[t]; sCol[t] = 0.f; }
    if (t == 0) sSq = 0.f;

    float acc[4][8];
    #pragma unroll
    for (int j = 0; j < 4; j++)
        #pragma unroll
        for (int i = 0; i < 8; i++) acc[j][i] = 0.f;

    int ty = t >> 4, tx = t & 15;
    __syncthreads();

    #pragma unroll 1
    for (int kc = 0; kc < 16; kc++) {
        const float4* w4 = (const float4*)(Wu + kc*16*EMB);
        ((float4*)Ws)[t]       = w4[t];
        ((float4*)Ws)[t + 256] = w4[t + 256];
        {
            int r = t >> 2, q = t & 3;
            int k = kc*16 + q*4;
            int node = n0 + r;
            const float* base = (k < 128) ? (g_h + node*EMB + k)
                                          : (g_magg + node*EMB + (k - 128));
            float4 v = *(const float4*)base;
            Xs[q*4+0][r] = v.x; Xs[q*4+1][r] = v.y;
            Xs[q*4+2][r] = v.z; Xs[q*4+3][r] = v.w;
        }
        __syncthreads();
        #pragma unroll
        for (int kk = 0; kk < 16; kk++) {
            float4 xv = *(const float4*)(&Xs[kk][ty*4]);
            float4 wa = *(const float4*)(&Ws[kk*EMB + tx*4]);
            float4 wb = *(const float4*)(&Ws[kk*EMB + 64 + tx*4]);
            float xs[4] = {xv.x, xv.y, xv.z, xv.w};
            float ws[8] = {wa.x, wa.y, wa.z, wa.w, wb.x, wb.y, wb.z, wb.w};
            #pragma unroll
            for (int j = 0; j < 4; j++)
                #pragma unroll
                for (int i = 0; i < 8; i++)
                    acc[j][i] = fmaf(xs[j], ws[i], acc[j][i]);
        }
        __syncthreads();
    }

    float sq = 0.f;
    #pragma unroll
    for (int j = 0; j < 4; j++) {
        int n = n0 + ty*4 + j;
        #pragma unroll
        for (int i = 0; i < 8; i++) {
            int c = (i < 4) ? tx*4 + i : 64 + tx*4 + (i - 4);
            float v = fmaxf(acc[j][i] + sBu[c], 0.f);
            acc[j][i] = v;
            sq += v*v;
        }
        float* o = g_h2 + (size_t)n*EMB;
        *(float4*)(o + tx*4)      = make_float4(acc[j][0], acc[j][1], acc[j][2], acc[j][3]);
        *(float4*)(o + 64 + tx*4) = make_float4(acc[j][4], acc[j][5], acc[j][6], acc[j][7]);
    }
    #pragma unroll
    for (int i = 0; i < 8; i++) {
        int c = (i < 4) ? tx*4 + i : 64 + tx*4 + (i - 4);
        atomicAdd(&sCol[c], acc[0][i] + acc[1][i] + acc[2][i] + acc[3][i]);
    }
    #pragma unroll
    for (int off = 16; off >= 1; off >>= 1)
        sq += __shfl_xor_sync(0xffffffffu, sq, off);
    if ((t & 31) == 0) atomicAdd(&sSq, sq);
    __syncthreads();
    if (t < 128) atomicAdd(&g_colsum[t], sCol[t]);
    if (t == 0)  atomicAdd(&g_sumsq, sSq);
}

__global__ void k_stats_zero()
{
    int t = threadIdx.x;
    if (t < 128) g_colsum[t] = 0.f;
    if (t == 0)  g_sumsq = 0.f;
}
__global__ void k_stats_final()
{
    __shared__ float red[4];
    int t = threadIdx.x;
    float mu = g_colsum[t] * (1.0f/(float)NTOT);
    g_mu[t] = mu;
    float m2 = mu*mu;
    #pragma unroll
    for (int off = 16; off >= 1; off >>= 1)
        m2 += __shfl_xor_sync(0xffffffffu, m2, off);
    if ((t & 31) == 0) red[t >> 5] = m2;
    __syncthreads();
    if (t == 0) {
        float tot = red[0] + red[1] + red[2] + red[3];
        float var = (g_sumsq - (float)NTOT * tot) * (1.0f/(float)NTOT) + 1e-5f;
        g_inv = 1.0f / sqrtf(var);
    }
}
__global__ void k_normalize()
{
    int idx = blockIdx.x*blockDim.x + threadIdx.x;
    if (idx >= NTOT*EMB) return;
    g_h[idx] = (g_h2[idx] - g_mu[idx & 127]) * g_inv;
}

// ----------------------------- readout ---------------------------------------------
__global__ void k_final(const float* __restrict__ W1, const float* __restrict__ b1,
                        const float* __restrict__ W2, const float* __restrict__ b2,
                        float* __restrict__ out)
{
    int g = blockIdx.x, c = threadIdx.x;
    const float* hb = g_h + (size_t)g*NG*EMB;
    float m0 = -3.4e38f, m1 = -3.4e38f, m2 = -3.4e38f, m3 = -3.4e38f;
    for (int n = 0; n < NG; n += 4) {
        m0 = fmaxf(m0, hb[(n+0)*EMB + c]);
        m1 = fmaxf(m1, hb[(n+1)*EMB + c]);
        m2 = fmaxf(m2, hb[(n+2)*EMB + c]);
        m3 = fmaxf(m3, hb[(n+3)*EMB + c]);
    }
    __shared__ float shg[128], shid[128];
    shg[c] = fmaxf(fmaxf(m0, m1), fmaxf(m2, m3));
    __syncthreads();
    float s = b1[c];
    #pragma unroll 4
    for (int k = 0; k < 128; k++) s += shg[k] * W1[k*EMB + c];
    shid[c] = fmaxf(s, 0.f);
    __syncthreads();
    if (c < 2) {
        float o = b2[c];
        for (int k = 0; k < 128; k++) o += shid[k] * W2[2*k + c];
        out[2*g + c] = o;
    }
}

// ----------------------------- launch sequence -------------------------------------
extern "C" void kernel_launch(void* const* d_in, const int* in_sizes, int n_in,
                              void* d_out, int out_size)
{
    const float* h_feat = (const float*)d_in[0];
    const float* pos    = (const float*)d_in[1];
    const int*   edge   = (const int*)  d_in[2];
    const float* W_emb  = (const float*)d_in[3];
    const float* b_emb  = (const float*)d_in[4];
    const float* W_msg  = (const float*)d_in[5];
    const float* b_msg  = (const float*)d_in[6];
    const float* W_pos  = (const float*)d_in[7];
    const float* b_pos  = (const float*)d_in[8];
    const float* W_upd  = (const float*)d_in[9];
    const float* b_upd  = (const float*)d_in[10];
    const float* W1     = (const float*)d_in[11];
    const float* b1     = (const float*)d_in[12];
    const float* W2     = (const float*)d_in[13];
    const float* b2     = (const float*)d_in[14];
    float* out = (float*)d_out;

    // resolve device-global pos buffers on host side via symbols
    static float* posbuf[2] = {nullptr, nullptr};
    if (!posbuf[0]) {
        cudaGetSymbolAddress((void**)&posbuf[0], g_posA);
        cudaGetSymbolAddress((void**)&posbuf[1], g_posB);
    }

    k_embed<<<(NTOT*EMB + 255)/256, 256>>>(h_feat, W_emb, b_emb);
    k_copy_pos<<<(NTOT*2 + 255)/256, 256>>>(pos);

    for (int l = 0; l < NLAYER; l++) {
        const float* pos_in  = posbuf[l & 1];
        float*       pos_out = posbuf[(l + 1) & 1];
        if (l == 0) {
            k_zero_csr<<<(NTOT + 255)/256, 256>>>();
            k_count<<<(EALL + 255)/256, 256>>>(edge + EALL);
            k_scan<<<1, 1024>>>();
            k_fill<<<(EALL + 255)/256, 256>>>(edge + EALL);
        } else {
            k_knn<<<BG*(NG/4), 128>>>(pos_in);
        }
        k_pgemm<<<2000, 256>>>(W_msg + (size_t)l*257*EMB, b_msg + l*EMB);
        k_edge<<<(NTOT*32 + 255)/256, 256>>>(
            l == 0 ? 1 : 0, edge,
            pos_in, pos_out,
            W_msg + (size_t)l*257*EMB + 256*EMB,
            W_pos + l*EMB*2, b_pos + l*2);
        k_stats_zero<<<1, 128>>>();
        k_update<<<NTOT/64, 256>>>(W_upd + (size_t)l*256*EMB, b_upd + l*EMB);
        k_stats_final<<<1, 128>>>();
        k_normalize<<<(NTOT*EMB + 255)/256, 256>>>();
    }
    k_final<<<BG, 128>>>(W1, b1, W2, b2, out);
}